// round 13
// baseline (speedup 1.0000x reference)
#include <cuda_runtime.h>
#include <cuda_fp16.h>
#include <cstdint>

#define N_NODES 50000
#define N_EDGES 800000
#define DIM 128
#define SCAN_NB ((N_NODES + 255) / 256)   // 196

// ---------------- scratch (static __device__ arrays; no allocation) ----------
__device__ int    g_deg[N_NODES];
__device__ float  g_dinv[N_NODES];
__device__ int    g_rowptr[N_NODES + 1];
__device__ int    g_cursor[N_NODES];
__device__ int    g_bsum[256];
__device__ int    g_csrsrc[N_EDGES];
__device__ float  g_csrw[N_EDGES];
__device__ __half g_h16[(size_t)N_NODES * DIM];   // fp16 gather source (both layers)
__device__ float  g_bufB[(size_t)N_NODES * DIM];  // h1 (fp32, gemm2 A source)
// B = W in mma fragment order, tf32 hi/lo:
// entry e = (ks*16 + ng)*32 + lane ; float2 = (val@k0, val@k0+4),
// k0 = ks*8 + (lane&3), n = ng*8 + (lane>>2)
__device__ float2 g_Bh[3][8192];
__device__ float2 g_Bl[3][8192];

__device__ __forceinline__ uint32_t tf32_hi_bits(float x) {
    uint32_t r;
    asm("cvt.rna.tf32.f32 %0, %1;" : "=r"(r) : "f"(x));
    return r;
}

// D += A(tf32) * B(tf32), m16n8k8
__device__ __forceinline__ void mma_tf32(float* c, const uint32_t* a,
                                         uint32_t b0, uint32_t b1) {
    asm volatile(
        "mma.sync.aligned.m16n8k8.row.col.f32.tf32.tf32.f32 "
        "{%0,%1,%2,%3}, {%4,%5,%6,%7}, {%8,%9}, {%0,%1,%2,%3};"
        : "+f"(c[0]), "+f"(c[1]), "+f"(c[2]), "+f"(c[3])
        : "r"(a[0]), "r"(a[1]), "r"(a[2]), "r"(a[3]), "r"(b0), "r"(b1));
}

// ---------------- weight pre-packing: fragment-ordered tf32 hi/lo -------------
__global__ void pack_w_kernel(const float* __restrict__ W1,
                              const float* __restrict__ W2,
                              const float* __restrict__ Wq) {
    int i = blockIdx.x * blockDim.x + threadIdx.x;
    if (i >= 3 * 8192) return;
    int w = i / 8192, e = i % 8192;
    int ks = e / 512, rem = e % 512;
    int ng = rem / 32, lane = rem % 32;
    int k0 = ks * 8 + (lane & 3);
    int n = ng * 8 + (lane >> 2);
    const float* Ws = (w == 0) ? W1 : (w == 1) ? W2 : Wq;
    float v0 = Ws[k0 * DIM + n];
    float v1 = Ws[(k0 + 4) * DIM + n];
    uint32_t h0 = tf32_hi_bits(v0), h1 = tf32_hi_bits(v1);
    uint32_t l0 = tf32_hi_bits(v0 - __uint_as_float(h0));
    uint32_t l1 = tf32_hi_bits(v1 - __uint_as_float(h1));
    g_Bh[w][e] = make_float2(__uint_as_float(h0), __uint_as_float(h1));
    g_Bl[w][e] = make_float2(__uint_as_float(l0), __uint_as_float(l1));
}

// ---------------- graph preprocessing ----------------------------------------
__global__ void init_deg_kernel() {
    int i = blockIdx.x * blockDim.x + threadIdx.x;
    if (i < N_NODES) g_deg[i] = 1;  // self-loop
}

// edge_index is int32 (JAX x64-disabled downcasts the declared int64)
__global__ void count_kernel(const int* __restrict__ ei) {
    int e = blockIdx.x * blockDim.x + threadIdx.x;
    if (e < N_EDGES) {
        unsigned d = (unsigned)ei[N_EDGES + e];
        if (d < N_NODES) atomicAdd(&g_deg[d], 1);
    }
}

__global__ void scan_phase1_kernel() {
    __shared__ int s[256];
    int t = threadIdx.x;
    int i = blockIdx.x * 256 + t;
    int deg = (i < N_NODES) ? g_deg[i] : 1;
    int val = deg - 1;
    s[t] = val;
    __syncthreads();
#pragma unroll
    for (int off = 1; off < 256; off <<= 1) {
        int v = (t >= off) ? s[t - off] : 0;
        __syncthreads();
        s[t] += v;
        __syncthreads();
    }
    if (i < N_NODES) {
        g_rowptr[i] = s[t] - val;
        g_cursor[i] = 0;
        g_dinv[i] = rsqrtf((float)deg);
    }
    if (t == 255) g_bsum[blockIdx.x] = s[255];
}

__global__ void scan_phase2_kernel() {
    __shared__ int s[256];
    int t = threadIdx.x;
    int v = (t < SCAN_NB) ? g_bsum[t] : 0;
    s[t] = v;
    __syncthreads();
#pragma unroll
    for (int off = 1; off < 256; off <<= 1) {
        int u = (t >= off) ? s[t - off] : 0;
        __syncthreads();
        s[t] += u;
        __syncthreads();
    }
    g_bsum[t] = s[t] - v;
}

__global__ void scan_phase3_kernel() {
    int i = blockIdx.x * 256 + threadIdx.x;
    if (i < N_NODES) g_rowptr[i] += g_bsum[blockIdx.x];
    if (i == 0) g_rowptr[N_NODES] = N_EDGES;
}

__global__ void scatter_kernel(const int* __restrict__ ei) {
    int e = blockIdx.x * blockDim.x + threadIdx.x;
    if (e < N_EDGES) {
        unsigned src = (unsigned)ei[e];
        unsigned dst = (unsigned)ei[N_EDGES + e];
        if (src < N_NODES && dst < N_NODES) {
            int pos = g_rowptr[dst] + atomicAdd(&g_cursor[dst], 1);
            g_csrsrc[pos] = src;
            g_csrw[pos] = g_dinv[src] * g_dinv[dst];
        }
    }
}

// ---------------- GEMM via mma.sync tf32 (3xTF32): C = A @ W (+bias) ----------
// block: 256 threads = 8 warps, tile 64 rows x 128 cols.
// SRC_BUF: 1 = read g_bufB (h1). DST: 0 = write fp16 g_h16, 1 = fp32 param C.
template <int WSEL, int SRC_BUF, int DST, bool ADD_BIAS>
__global__ void __launch_bounds__(256)
gemm_mma_kernel(const float* __restrict__ A,
                const float* __restrict__ bias,
                float* __restrict__ C, int M) {
    __shared__ float sA[64][132];   // pad 132 -> conflict-free fragment LDS

    const int tid = threadIdx.x;
    const int wid = tid >> 5;
    const int lane = tid & 31;
    const int gid = lane >> 2;      // group id (0..7)
    const int tid4 = lane & 3;      // thread-in-group (0..3)
    const int warpM = (wid & 1) * 32;
    const int warpNg = wid >> 1;    // 0..3 (n-offset = warpNg*32)
    const int row0 = blockIdx.x * 64;

    // load A tile (64x128) -> SMEM
    const float* Abase = SRC_BUF ? g_bufB : A;
    const float4* A4 = (const float4*)Abase;
#pragma unroll
    for (int t = 0; t < 8; t++) {
        int idx = tid + t * 256;          // 0..2047
        int r = idx >> 5, c = idx & 31;
        float4 v = make_float4(0.f, 0.f, 0.f, 0.f);
        if (row0 + r < M) v = A4[(size_t)(row0 + r) * 32 + c];
        *(float4*)&sA[r][c * 4] = v;
    }
    __syncthreads();

    float acc[2][4][4];
#pragma unroll
    for (int mt = 0; mt < 2; mt++)
#pragma unroll
        for (int nt = 0; nt < 4; nt++)
#pragma unroll
            for (int k = 0; k < 4; k++) acc[mt][nt][k] = 0.f;

#pragma unroll 2
    for (int ks = 0; ks < 16; ks++) {
        uint32_t ah[2][4], al[2][4];
#pragma unroll
        for (int mt = 0; mt < 2; mt++) {
            int rb = warpM + mt * 16;
            int col = ks * 8 + tid4;
            float v0 = sA[rb + gid][col];
            float v1 = sA[rb + gid + 8][col];
            float v2 = sA[rb + gid][col + 4];
            float v3 = sA[rb + gid + 8][col + 4];
            ah[mt][0] = tf32_hi_bits(v0);
            ah[mt][1] = tf32_hi_bits(v1);
            ah[mt][2] = tf32_hi_bits(v2);
            ah[mt][3] = tf32_hi_bits(v3);
            al[mt][0] = tf32_hi_bits(v0 - __uint_as_float(ah[mt][0]));
            al[mt][1] = tf32_hi_bits(v1 - __uint_as_float(ah[mt][1]));
            al[mt][2] = tf32_hi_bits(v2 - __uint_as_float(ah[mt][2]));
            al[mt][3] = tf32_hi_bits(v3 - __uint_as_float(ah[mt][3]));
        }
#pragma unroll
        for (int nt = 0; nt < 4; nt++) {
            int ng = warpNg * 4 + nt;
            float2 bh = __ldg(&g_Bh[WSEL][(ks * 16 + ng) * 32 + lane]);
            float2 bl = __ldg(&g_Bl[WSEL][(ks * 16 + ng) * 32 + lane]);
            uint32_t bh0 = __float_as_uint(bh.x), bh1 = __float_as_uint(bh.y);
            uint32_t bl0 = __float_as_uint(bl.x), bl1 = __float_as_uint(bl.y);
#pragma unroll
            for (int mt = 0; mt < 2; mt++) {
                mma_tf32(acc[mt][nt], ah[mt], bh0, bh1);  // Ah*Bh
                mma_tf32(acc[mt][nt], al[mt], bh0, bh1);  // Al*Bh
                mma_tf32(acc[mt][nt], ah[mt], bl0, bl1);  // Ah*Bl
            }
        }
    }

    // epilogue
#pragma unroll
    for (int mt = 0; mt < 2; mt++) {
#pragma unroll
        for (int nt = 0; nt < 4; nt++) {
            int col = warpNg * 32 + nt * 8 + tid4 * 2;
            float bx = 0.f, by = 0.f;
            if (ADD_BIAS) {
                float2 bv = ((const float2*)bias)[col >> 1];
                bx = bv.x; by = bv.y;
            }
            int r0 = row0 + warpM + mt * 16 + gid;
#pragma unroll
            for (int half = 0; half < 2; half++) {
                int r = r0 + half * 8;
                if (r < M) {
                    float ox = acc[mt][nt][2 * half + 0] + bx;
                    float oy = acc[mt][nt][2 * half + 1] + by;
                    if (DST) {
                        *(float2*)&C[(size_t)r * DIM + col] = make_float2(ox, oy);
                    } else {
                        *(__half2*)&g_h16[(size_t)r * DIM + col] =
                            __floats2half2_rn(ox, oy);
                    }
                }
            }
        }
    }
}

// ---------------- aggregation: fp16 gather, fp32 accumulate -------------------
// reads g_h16; DST_BUF: 1 = write g_bufB (fp32), 0 = write param out (fp32)
// block = (32,8): 32 lanes (4 feats = uint2 per lane) x 8 nodes per block
template <int DST_BUF, bool RELU>
__global__ void aggregate_kernel(const float* __restrict__ bias,
                                 float* __restrict__ out) {
    int node = blockIdx.x * 8 + threadIdx.y;
    if (node >= N_NODES) return;
    int lane = threadIdx.x;

    const uint2* H = (const uint2*)g_h16;   // 4 halves per uint2; 32 per row
    float di = g_dinv[node];
    float w0 = di * di;

    uint2 hs = H[(size_t)node * 32 + lane];
    float2 f01 = __half22float2(*(__half2*)&hs.x);
    float2 f23 = __half22float2(*(__half2*)&hs.y);
    float4 acc = make_float4(f01.x * w0, f01.y * w0, f23.x * w0, f23.y * w0);

    int beg = g_rowptr[node];
    int end = g_rowptr[node + 1];
    int j = beg;
    for (; j + 3 < end; j += 4) {
        int s0 = g_csrsrc[j];
        int s1 = g_csrsrc[j + 1];
        int s2 = g_csrsrc[j + 2];
        int s3 = g_csrsrc[j + 3];
        float wa = g_csrw[j];
        float wb = g_csrw[j + 1];
        float wc = g_csrw[j + 2];
        float wd = g_csrw[j + 3];
        uint2 r0 = H[(size_t)s0 * 32 + lane];
        uint2 r1 = H[(size_t)s1 * 32 + lane];
        uint2 r2 = H[(size_t)s2 * 32 + lane];
        uint2 r3 = H[(size_t)s3 * 32 + lane];
        float2 a01 = __half22float2(*(__half2*)&r0.x);
        float2 a23 = __half22float2(*(__half2*)&r0.y);
        float2 b01 = __half22float2(*(__half2*)&r1.x);
        float2 b23 = __half22float2(*(__half2*)&r1.y);
        float2 c01 = __half22float2(*(__half2*)&r2.x);
        float2 c23 = __half22float2(*(__half2*)&r2.y);
        float2 d01 = __half22float2(*(__half2*)&r3.x);
        float2 d23 = __half22float2(*(__half2*)&r3.y);
        acc.x += a01.x * wa; acc.y += a01.y * wa;
        acc.z += a23.x * wa; acc.w += a23.y * wa;
        acc.x += b01.x * wb; acc.y += b01.y * wb;
        acc.z += b23.x * wb; acc.w += b23.y * wb;
        acc.x += c01.x * wc; acc.y += c01.y * wc;
        acc.z += c23.x * wc; acc.w += c23.y * wc;
        acc.x += d01.x * wd; acc.y += d01.y * wd;
        acc.z += d23.x * wd; acc.w += d23.y * wd;
    }
    for (; j < end; j++) {
        int s = g_csrsrc[j];
        float w = g_csrw[j];
        uint2 r = H[(size_t)s * 32 + lane];
        float2 v01 = __half22float2(*(__half2*)&r.x);
        float2 v23 = __half22float2(*(__half2*)&r.y);
        acc.x += v01.x * w; acc.y += v01.y * w;
        acc.z += v23.x * w; acc.w += v23.y * w;
    }

    float4 bv = ((const float4*)bias)[lane];
    acc.x += bv.x; acc.y += bv.y; acc.z += bv.z; acc.w += bv.w;
    if (RELU) {
        acc.x = fmaxf(acc.x, 0.f);
        acc.y = fmaxf(acc.y, 0.f);
        acc.z = fmaxf(acc.z, 0.f);
        acc.w = fmaxf(acc.w, 0.f);
    }
    float4* O = DST_BUF ? (float4*)g_bufB : (float4*)out;
    O[(size_t)node * 32 + lane] = acc;
}

// ---------------- launch (serial chain) ---------------------------------------
extern "C" void kernel_launch(void* const* d_in, const int* in_sizes, int n_in,
                              void* d_out, int out_size) {
    const float* x    = (const float*)d_in[0];
    const int*   ei   = (const int*)d_in[1];
    const float* qemb = (const float*)d_in[2];
    const float* W1   = (const float*)d_in[3];
    const float* b1   = (const float*)d_in[4];
    const float* W2   = (const float*)d_in[5];
    const float* b2   = (const float*)d_in[6];
    const float* Wq   = (const float*)d_in[7];
    const float* bq   = (const float*)d_in[8];

    float* out = (float*)d_out;
    float* out_ques = out;                          // [20000,128]
    float* out_h2   = out + (size_t)20000 * DIM;    // [50000,128]

    // weight packing + graph preprocessing
    pack_w_kernel<<<(3 * 8192 + 255) / 256, 256>>>(W1, W2, Wq);
    init_deg_kernel<<<(N_NODES + 255) / 256, 256>>>();
    count_kernel<<<(N_EDGES + 255) / 256, 256>>>(ei);
    scan_phase1_kernel<<<SCAN_NB, 256>>>();
    scan_phase2_kernel<<<1, 256>>>();
    scan_phase3_kernel<<<SCAN_NB, 256>>>();
    scatter_kernel<<<(N_EDGES + 255) / 256, 256>>>(ei);

    // layer 1: g_h16 = fp16(x @ W1) ; g_bufB = relu(agg(g_h16) + b1)  [fp32]
    gemm_mma_kernel<0, 0, 0, false><<<(N_NODES + 63) / 64, 256>>>(x, nullptr, nullptr, N_NODES);
    aggregate_kernel<1, true><<<(N_NODES + 7) / 8, dim3(32, 8)>>>(b1, nullptr);
    // layer 2: g_h16 = fp16(g_bufB @ W2) ; out_h2 = agg(g_h16) + b2
    gemm_mma_kernel<1, 1, 0, false><<<(N_NODES + 63) / 64, 256>>>(nullptr, nullptr, nullptr, N_NODES);
    aggregate_kernel<0, false><<<(N_NODES + 7) / 8, dim3(32, 8)>>>(b2, out_h2);
    // question path: ques = q_emb @ Wq + bq
    gemm_mma_kernel<2, 0, 1, true><<<(20000 + 63) / 64, 256>>>(qemb, bq, out_ques, 20000);
}

// round 14
// speedup vs baseline: 1.4096x; 1.4096x over previous
#include <cuda_runtime.h>
#include <cstdint>

#define N_NODES 50000
#define N_EDGES 800000
#define DIM 128
#define SCAN_NB ((N_NODES + 255) / 256)   // 196

// ---------------- scratch (static __device__ arrays; no allocation) ----------
__device__ int   g_deg[N_NODES];          // edge-count; self-resetting per launch
__device__ float g_dinv[N_NODES];
__device__ int   g_rowptr[N_NODES + 1];
__device__ int   g_cursor[N_NODES];
__device__ int   g_bsum[256];
__device__ int2  g_csre[N_EDGES];         // (src, weight-bits) packed
__device__ float g_bufA[(size_t)N_NODES * DIM];  // GEMM outputs
__device__ float g_bufB[(size_t)N_NODES * DIM];  // h1
// B = W in mma fragment order, tf32 hi/lo:
// entry e = (ks*16 + ng)*32 + lane ; float2 = (val@k0, val@k0+4),
// k0 = ks*8 + (lane&3), n = ng*8 + (lane>>2)
__device__ float2 g_Bh[3][8192];
__device__ float2 g_Bl[3][8192];

__device__ __forceinline__ uint32_t tf32_hi_bits(float x) {
    uint32_t r;
    asm("cvt.rna.tf32.f32 %0, %1;" : "=r"(r) : "f"(x));
    return r;
}

// D += A(tf32) * B(tf32), m16n8k8
__device__ __forceinline__ void mma_tf32(float* c, const uint32_t* a,
                                         uint32_t b0, uint32_t b1) {
    asm volatile(
        "mma.sync.aligned.m16n8k8.row.col.f32.tf32.tf32.f32 "
        "{%0,%1,%2,%3}, {%4,%5,%6,%7}, {%8,%9}, {%0,%1,%2,%3};"
        : "+f"(c[0]), "+f"(c[1]), "+f"(c[2]), "+f"(c[3])
        : "r"(a[0]), "r"(a[1]), "r"(a[2]), "r"(a[3]), "r"(b0), "r"(b1));
}

// ---------------- weight pre-packing: fragment-ordered tf32 hi/lo -------------
__global__ void pack_w_kernel(const float* __restrict__ W1,
                              const float* __restrict__ W2,
                              const float* __restrict__ Wq) {
    int i = blockIdx.x * blockDim.x + threadIdx.x;
    if (i >= 3 * 8192) return;
    int w = i / 8192, e = i % 8192;
    int ks = e / 512, rem = e % 512;
    int ng = rem / 32, lane = rem % 32;
    int k0 = ks * 8 + (lane & 3);
    int n = ng * 8 + (lane >> 2);
    const float* Ws = (w == 0) ? W1 : (w == 1) ? W2 : Wq;
    float v0 = Ws[k0 * DIM + n];
    float v1 = Ws[(k0 + 4) * DIM + n];
    uint32_t h0 = tf32_hi_bits(v0), h1 = tf32_hi_bits(v1);
    uint32_t l0 = tf32_hi_bits(v0 - __uint_as_float(h0));
    uint32_t l1 = tf32_hi_bits(v1 - __uint_as_float(h1));
    g_Bh[w][e] = make_float2(__uint_as_float(h0), __uint_as_float(h1));
    g_Bl[w][e] = make_float2(__uint_as_float(l0), __uint_as_float(l1));
}

// ---------------- graph preprocessing ----------------------------------------
// edge_index is int32 (JAX x64-disabled downcasts the declared int64).
// g_deg starts zero (module load) and is reset to zero by scan_phase1 each
// launch, so no init kernel is needed.
__global__ void count_kernel(const int* __restrict__ ei) {
    int e = blockIdx.x * blockDim.x + threadIdx.x;
    if (e < N_EDGES) {
        unsigned d = (unsigned)ei[N_EDGES + e];
        if (d < N_NODES) atomicAdd(&g_deg[d], 1);
    }
}

__global__ void scan_phase1_kernel() {
    __shared__ int s[256];
    int t = threadIdx.x;
    int i = blockIdx.x * 256 + t;
    int cnt = 0;
    if (i < N_NODES) {
        cnt = g_deg[i];          // edge count (no self-loop)
        g_deg[i] = 0;            // self-reset for next graph replay
    }
    s[t] = cnt;
    __syncthreads();
#pragma unroll
    for (int off = 1; off < 256; off <<= 1) {
        int v = (t >= off) ? s[t - off] : 0;
        __syncthreads();
        s[t] += v;
        __syncthreads();
    }
    if (i < N_NODES) {
        g_rowptr[i] = s[t] - cnt;   // block-local exclusive prefix
        g_cursor[i] = 0;
        g_dinv[i] = rsqrtf((float)(cnt + 1));   // deg incl. self-loop
    }
    if (t == 255) g_bsum[blockIdx.x] = s[255];
}

__global__ void scan_phase2_kernel() {
    __shared__ int s[256];
    int t = threadIdx.x;
    int v = (t < SCAN_NB) ? g_bsum[t] : 0;
    s[t] = v;
    __syncthreads();
#pragma unroll
    for (int off = 1; off < 256; off <<= 1) {
        int u = (t >= off) ? s[t - off] : 0;
        __syncthreads();
        s[t] += u;
        __syncthreads();
    }
    g_bsum[t] = s[t] - v;
}

__global__ void scan_phase3_kernel() {
    int i = blockIdx.x * 256 + threadIdx.x;
    if (i < N_NODES) g_rowptr[i] += g_bsum[blockIdx.x];
    if (i == 0) g_rowptr[N_NODES] = N_EDGES;
}

__global__ void scatter_kernel(const int* __restrict__ ei) {
    int e = blockIdx.x * blockDim.x + threadIdx.x;
    if (e < N_EDGES) {
        unsigned src = (unsigned)ei[e];
        unsigned dst = (unsigned)ei[N_EDGES + e];
        if (src < N_NODES && dst < N_NODES) {
            int pos = g_rowptr[dst] + atomicAdd(&g_cursor[dst], 1);
            float w = g_dinv[src] * g_dinv[dst];
            g_csre[pos] = make_int2((int)src, __float_as_int(w));
        }
    }
}

// ---------------- GEMM via mma.sync tf32 (3xTF32): C = A @ W (+bias) ----------
// block: 256 threads = 8 warps, tile 64 rows x 128 cols.
// warp grid: 2 (M) x 4 (N); warp tile 32x32 = 2 mtiles x 4 ntiles of m16n8k8.
template <int WSEL, int SRC_BUF, int DST, bool ADD_BIAS>
__global__ void __launch_bounds__(256)
gemm_mma_kernel(const float* __restrict__ A,
                const float* __restrict__ bias,
                float* __restrict__ C, int M) {
    __shared__ float sA[64][132];   // pad 132 -> conflict-free fragment LDS

    const int tid = threadIdx.x;
    const int wid = tid >> 5;
    const int lane = tid & 31;
    const int gid = lane >> 2;      // group id (0..7)
    const int tid4 = lane & 3;      // thread-in-group (0..3)
    const int warpM = (wid & 1) * 32;
    const int warpNg = wid >> 1;    // 0..3 (n-offset = warpNg*32)
    const int row0 = blockIdx.x * 64;

    // load A tile (64x128) -> SMEM
    const float* Abase = SRC_BUF ? g_bufB : A;
    const float4* A4 = (const float4*)Abase;
#pragma unroll
    for (int t = 0; t < 8; t++) {
        int idx = tid + t * 256;          // 0..2047
        int r = idx >> 5, c = idx & 31;
        float4 v = make_float4(0.f, 0.f, 0.f, 0.f);
        if (row0 + r < M) v = A4[(size_t)(row0 + r) * 32 + c];
        *(float4*)&sA[r][c * 4] = v;
    }
    __syncthreads();

    float acc[2][4][4];
#pragma unroll
    for (int mt = 0; mt < 2; mt++)
#pragma unroll
        for (int nt = 0; nt < 4; nt++)
#pragma unroll
            for (int k = 0; k < 4; k++) acc[mt][nt][k] = 0.f;

#pragma unroll 2
    for (int ks = 0; ks < 16; ks++) {
        uint32_t ah[2][4], al[2][4];
#pragma unroll
        for (int mt = 0; mt < 2; mt++) {
            int rb = warpM + mt * 16;
            int col = ks * 8 + tid4;
            float v0 = sA[rb + gid][col];
            float v1 = sA[rb + gid + 8][col];
            float v2 = sA[rb + gid][col + 4];
            float v3 = sA[rb + gid + 8][col + 4];
            ah[mt][0] = tf32_hi_bits(v0);
            ah[mt][1] = tf32_hi_bits(v1);
            ah[mt][2] = tf32_hi_bits(v2);
            ah[mt][3] = tf32_hi_bits(v3);
            al[mt][0] = tf32_hi_bits(v0 - __uint_as_float(ah[mt][0]));
            al[mt][1] = tf32_hi_bits(v1 - __uint_as_float(ah[mt][1]));
            al[mt][2] = tf32_hi_bits(v2 - __uint_as_float(ah[mt][2]));
            al[mt][3] = tf32_hi_bits(v3 - __uint_as_float(ah[mt][3]));
        }
#pragma unroll
        for (int nt = 0; nt < 4; nt++) {
            int ng = warpNg * 4 + nt;
            float2 bh = __ldg(&g_Bh[WSEL][(ks * 16 + ng) * 32 + lane]);
            float2 bl = __ldg(&g_Bl[WSEL][(ks * 16 + ng) * 32 + lane]);
            uint32_t bh0 = __float_as_uint(bh.x), bh1 = __float_as_uint(bh.y);
            uint32_t bl0 = __float_as_uint(bl.x), bl1 = __float_as_uint(bl.y);
#pragma unroll
            for (int mt = 0; mt < 2; mt++) {
                mma_tf32(acc[mt][nt], ah[mt], bh0, bh1);  // Ah*Bh
                mma_tf32(acc[mt][nt], al[mt], bh0, bh1);  // Al*Bh
                mma_tf32(acc[mt][nt], ah[mt], bl0, bl1);  // Ah*Bl
            }
        }
    }

    // epilogue
    float* Cout = DST ? C : g_bufA;
#pragma unroll
    for (int mt = 0; mt < 2; mt++) {
#pragma unroll
        for (int nt = 0; nt < 4; nt++) {
            int col = warpNg * 32 + nt * 8 + tid4 * 2;
            float bx = 0.f, by = 0.f;
            if (ADD_BIAS) {
                float2 bv = ((const float2*)bias)[col >> 1];
                bx = bv.x; by = bv.y;
            }
            int r0 = row0 + warpM + mt * 16 + gid;
            if (r0 < M) {
                float2 o = make_float2(acc[mt][nt][0] + bx, acc[mt][nt][1] + by);
                *(float2*)&Cout[(size_t)r0 * DIM + col] = o;
            }
            if (r0 + 8 < M) {
                float2 o = make_float2(acc[mt][nt][2] + bx, acc[mt][nt][3] + by);
                *(float2*)&Cout[(size_t)(r0 + 8) * DIM + col] = o;
            }
        }
    }
}

// ---------------- aggregation: out[i] = sum_j norm*h[src] + self + bias -------
// 4-deep unrolled CSR walk; packed (src, weight) int2 edge records
template <int DST_BUF, bool RELU>
__global__ void aggregate_kernel(const float* __restrict__ bias,
                                 float* __restrict__ out) {
    int node = blockIdx.x * 8 + threadIdx.y;
    if (node >= N_NODES) return;
    int lane = threadIdx.x;

    const float4* H4 = (const float4*)g_bufA;
    float di = g_dinv[node];
    float w0 = di * di;
    float4 h = H4[(size_t)node * 32 + lane];
    float4 acc = make_float4(h.x * w0, h.y * w0, h.z * w0, h.w * w0);

    int beg = g_rowptr[node];
    int end = g_rowptr[node + 1];
    int j = beg;
    for (; j + 3 < end; j += 4) {
        int2 e0 = g_csre[j];
        int2 e1 = g_csre[j + 1];
        int2 e2 = g_csre[j + 2];
        int2 e3 = g_csre[j + 3];
        float wa = __int_as_float(e0.y);
        float wb = __int_as_float(e1.y);
        float wc = __int_as_float(e2.y);
        float wd = __int_as_float(e3.y);
        float4 v0 = H4[(size_t)e0.x * 32 + lane];
        float4 v1 = H4[(size_t)e1.x * 32 + lane];
        float4 v2 = H4[(size_t)e2.x * 32 + lane];
        float4 v3 = H4[(size_t)e3.x * 32 + lane];
        acc.x += v0.x * wa; acc.y += v0.y * wa;
        acc.z += v0.z * wa; acc.w += v0.w * wa;
        acc.x += v1.x * wb; acc.y += v1.y * wb;
        acc.z += v1.z * wb; acc.w += v1.w * wb;
        acc.x += v2.x * wc; acc.y += v2.y * wc;
        acc.z += v2.z * wc; acc.w += v2.w * wc;
        acc.x += v3.x * wd; acc.y += v3.y * wd;
        acc.z += v3.z * wd; acc.w += v3.w * wd;
    }
    for (; j < end; j++) {
        int2 e = g_csre[j];
        float w = __int_as_float(e.y);
        float4 v = H4[(size_t)e.x * 32 + lane];
        acc.x += v.x * w; acc.y += v.y * w;
        acc.z += v.z * w; acc.w += v.w * w;
    }

    float4 bv = ((const float4*)bias)[lane];
    acc.x += bv.x; acc.y += bv.y; acc.z += bv.z; acc.w += bv.w;
    if (RELU) {
        acc.x = fmaxf(acc.x, 0.f);
        acc.y = fmaxf(acc.y, 0.f);
        acc.z = fmaxf(acc.z, 0.f);
        acc.w = fmaxf(acc.w, 0.f);
    }
    float4* O = DST_BUF ? (float4*)g_bufB : (float4*)out;
    O[(size_t)node * 32 + lane] = acc;
}

// ---------------- launch (serial chain) ---------------------------------------
extern "C" void kernel_launch(void* const* d_in, const int* in_sizes, int n_in,
                              void* d_out, int out_size) {
    const float* x    = (const float*)d_in[0];
    const int*   ei   = (const int*)d_in[1];
    const float* qemb = (const float*)d_in[2];
    const float* W1   = (const float*)d_in[3];
    const float* b1   = (const float*)d_in[4];
    const float* W2   = (const float*)d_in[5];
    const float* b2   = (const float*)d_in[6];
    const float* Wq   = (const float*)d_in[7];
    const float* bq   = (const float*)d_in[8];

    float* out = (float*)d_out;
    float* out_ques = out;                          // [20000,128]
    float* out_h2   = out + (size_t)20000 * DIM;    // [50000,128]

    // weight packing + graph preprocessing (g_deg self-resets; no init kernel)
    pack_w_kernel<<<(3 * 8192 + 255) / 256, 256>>>(W1, W2, Wq);
    count_kernel<<<(N_EDGES + 255) / 256, 256>>>(ei);
    scan_phase1_kernel<<<SCAN_NB, 256>>>();
    scan_phase2_kernel<<<1, 256>>>();
    scan_phase3_kernel<<<SCAN_NB, 256>>>();
    scatter_kernel<<<(N_EDGES + 255) / 256, 256>>>(ei);

    // layer 1: g_bufA = x @ W1 ; g_bufB = relu(agg(g_bufA) + b1)
    gemm_mma_kernel<0, 0, 0, false><<<(N_NODES + 63) / 64, 256>>>(x, nullptr, nullptr, N_NODES);
    aggregate_kernel<1, true><<<(N_NODES + 7) / 8, dim3(32, 8)>>>(b1, nullptr);
    // layer 2: g_bufA = g_bufB @ W2 ; out_h2 = agg(g_bufA) + b2
    gemm_mma_kernel<1, 1, 0, false><<<(N_NODES + 63) / 64, 256>>>(nullptr, nullptr, nullptr, N_NODES);
    aggregate_kernel<0, false><<<(N_NODES + 7) / 8, dim3(32, 8)>>>(b2, out_h2);
    // question path: ques = q_emb @ Wq + bq
    gemm_mma_kernel<2, 0, 1, true><<<(20000 + 63) / 64, 256>>>(qemb, bq, out_ques, 20000);
}

// round 17
// speedup vs baseline: 1.4184x; 1.0063x over previous
#include <cuda_runtime.h>
#include <cstdint>

#define N_NODES 50000
#define N_EDGES 800000
#define DIM 128
#define SCAN_NB ((N_NODES + 255) / 256)   // 196

// ---------------- scratch (static __device__ arrays; no allocation) ----------
__device__ int   g_deg[N_NODES];          // edge-count; self-resetting per launch
__device__ float g_dinv[N_NODES];
__device__ int   g_rowptr[N_NODES];       // start of node's edge range
__device__ int   g_rowend[N_NODES];       // end of node's edge range
__device__ int   g_cursor[N_NODES];
__device__ int   g_total;                 // global edge-offset counter
__device__ int2  g_csre[N_EDGES];         // (src, weight-bits) packed
__device__ float g_bufA[(size_t)N_NODES * DIM];  // GEMM outputs
__device__ float g_bufB[(size_t)N_NODES * DIM];  // h1
// B = W in mma fragment order, tf32 hi/lo:
// entry e = (ks*16 + ng)*32 + lane ; float2 = (val@k0, val@k0+4),
// k0 = ks*8 + (lane&3), n = ng*8 + (lane>>2)
__device__ float2 g_Bh[3][8192];
__device__ float2 g_Bl[3][8192];

__device__ __forceinline__ uint32_t tf32_hi_bits(float x) {
    uint32_t r;
    asm("cvt.rna.tf32.f32 %0, %1;" : "=r"(r) : "f"(x));
    return r;
}

// D += A(tf32) * B(tf32), m16n8k8
__device__ __forceinline__ void mma_tf32(float* c, const uint32_t* a,
                                         uint32_t b0, uint32_t b1) {
    asm volatile(
        "mma.sync.aligned.m16n8k8.row.col.f32.tf32.tf32.f32 "
        "{%0,%1,%2,%3}, {%4,%5,%6,%7}, {%8,%9}, {%0,%1,%2,%3};"
        : "+f"(c[0]), "+f"(c[1]), "+f"(c[2]), "+f"(c[3])
        : "r"(a[0]), "r"(a[1]), "r"(a[2]), "r"(a[3]), "r"(b0), "r"(b1));
}

// ---------------- weight pre-packing: fragment-ordered tf32 hi/lo -------------
__global__ void pack_w_kernel(const float* __restrict__ W1,
                              const float* __restrict__ W2,
                              const float* __restrict__ Wq) {
    int i = blockIdx.x * blockDim.x + threadIdx.x;
    if (i >= 3 * 8192) return;
    int w = i / 8192, e = i % 8192;
    int ks = e / 512, rem = e % 512;
    int ng = rem / 32, lane = rem % 32;
    int k0 = ks * 8 + (lane & 3);
    int n = ng * 8 + (lane >> 2);
    const float* Ws = (w == 0) ? W1 : (w == 1) ? W2 : Wq;
    float v0 = Ws[k0 * DIM + n];
    float v1 = Ws[(k0 + 4) * DIM + n];
    uint32_t h0 = tf32_hi_bits(v0), h1 = tf32_hi_bits(v1);
    uint32_t l0 = tf32_hi_bits(v0 - __uint_as_float(h0));
    uint32_t l1 = tf32_hi_bits(v1 - __uint_as_float(h1));
    g_Bh[w][e] = make_float2(__uint_as_float(h0), __uint_as_float(h1));
    g_Bl[w][e] = make_float2(__uint_as_float(l0), __uint_as_float(l1));
}

// ---------------- graph preprocessing ----------------------------------------
// edge_index is int32 (JAX x64-disabled downcasts the declared int64).
// g_deg starts zero (module load) and is reset by scan_kernel each launch.
// g_total is reset by count_kernel thread 0 (serial launch order).
__global__ void count_kernel(const int* __restrict__ ei) {
    int e = blockIdx.x * blockDim.x + threadIdx.x;
    if (e == 0) g_total = 0;
    if (e < N_EDGES) {
        unsigned d = (unsigned)ei[N_EDGES + e];
        if (d < N_NODES) atomicAdd(&g_deg[d], 1);
    }
}

// single-kernel scan: block-local prefix + atomic global base.
// Global node ordering of ranges is irrelevant — only contiguity per node.
__global__ void scan_kernel() {
    __shared__ int s[256];
    __shared__ int s_base;
    int t = threadIdx.x;
    int i = blockIdx.x * 256 + t;
    int cnt = 0;
    if (i < N_NODES) {
        cnt = g_deg[i];          // edge count (no self-loop)
        g_deg[i] = 0;            // self-reset for next graph replay
    }
    s[t] = cnt;
    __syncthreads();
#pragma unroll
    for (int off = 1; off < 256; off <<= 1) {
        int v = (t >= off) ? s[t - off] : 0;
        __syncthreads();
        s[t] += v;
        __syncthreads();
    }
    if (t == 255) s_base = atomicAdd(&g_total, s[255]);
    __syncthreads();
    if (i < N_NODES) {
        int start = s_base + s[t] - cnt;
        g_rowptr[i] = start;
        g_rowend[i] = start + cnt;
        g_cursor[i] = 0;
        g_dinv[i] = rsqrtf((float)(cnt + 1));   // deg incl. self-loop
    }
}

// 2 edges per thread for extra atomic/store MLP
__global__ void scatter_kernel(const int* __restrict__ ei) {
    int base = (blockIdx.x * blockDim.x + threadIdx.x) * 2;
#pragma unroll
    for (int u = 0; u < 2; u++) {
        int e = base + u;
        if (e < N_EDGES) {
            unsigned src = (unsigned)ei[e];
            unsigned dst = (unsigned)ei[N_EDGES + e];
            if (src < N_NODES && dst < N_NODES) {
                int pos = g_rowptr[dst] + atomicAdd(&g_cursor[dst], 1);
                float w = g_dinv[src] * g_dinv[dst];
                g_csre[pos] = make_int2((int)src, __float_as_int(w));
            }
        }
    }
}

// ---------------- GEMM via mma.sync tf32 (3xTF32): C = A @ W (+bias) ----------
// block: 256 threads = 8 warps, tile 64 rows x 128 cols.
// warp grid: 2 (M) x 4 (N); warp tile 32x32 = 2 mtiles x 4 ntiles of m16n8k8.
template <int WSEL, int SRC_BUF, int DST, bool ADD_BIAS>
__global__ void __launch_bounds__(256)
gemm_mma_kernel(const float* __restrict__ A,
                const float* __restrict__ bias,
                float* __restrict__ C, int M) {
    __shared__ float sA[64][132];   // pad 132 -> conflict-free fragment LDS

    const int tid = threadIdx.x;
    const int wid = tid >> 5;
    const int lane = tid & 31;
    const int gid = lane >> 2;      // group id (0..7)
    const int tid4 = lane & 3;      // thread-in-group (0..3)
    const int warpM = (wid & 1) * 32;
    const int warpNg = wid >> 1;    // 0..3 (n-offset = warpNg*32)
    const int row0 = blockIdx.x * 64;

    // load A tile (64x128) -> SMEM
    const float* Abase = SRC_BUF ? g_bufB : A;
    const float4* A4 = (const float4*)Abase;
#pragma unroll
    for (int t = 0; t < 8; t++) {
        int idx = tid + t * 256;          // 0..2047
        int r = idx >> 5, c = idx & 31;
        float4 v = make_float4(0.f, 0.f, 0.f, 0.f);
        if (row0 + r < M) v = A4[(size_t)(row0 + r) * 32 + c];
        *(float4*)&sA[r][c * 4] = v;
    }
    __syncthreads();

    float acc[2][4][4];
#pragma unroll
    for (int mt = 0; mt < 2; mt++)
#pragma unroll
        for (int nt = 0; nt < 4; nt++)
#pragma unroll
            for (int k = 0; k < 4; k++) acc[mt][nt][k] = 0.f;

#pragma unroll 2
    for (int ks = 0; ks < 16; ks++) {
        uint32_t ah[2][4], al[2][4];
#pragma unroll
        for (int mt = 0; mt < 2; mt++) {
            int rb = warpM + mt * 16;
            int col = ks * 8 + tid4;
            float v0 = sA[rb + gid][col];
            float v1 = sA[rb + gid + 8][col];
            float v2 = sA[rb + gid][col + 4];
            float v3 = sA[rb + gid + 8][col + 4];
            ah[mt][0] = tf32_hi_bits(v0);
            ah[mt][1] = tf32_hi_bits(v1);
            ah[mt][2] = tf32_hi_bits(v2);
            ah[mt][3] = tf32_hi_bits(v3);
            al[mt][0] = tf32_hi_bits(v0 - __uint_as_float(ah[mt][0]));
            al[mt][1] = tf32_hi_bits(v1 - __uint_as_float(ah[mt][1]));
            al[mt][2] = tf32_hi_bits(v2 - __uint_as_float(ah[mt][2]));
            al[mt][3] = tf32_hi_bits(v3 - __uint_as_float(ah[mt][3]));
        }
#pragma unroll
        for (int nt = 0; nt < 4; nt++) {
            int ng = warpNg * 4 + nt;
            float2 bh = __ldg(&g_Bh[WSEL][(ks * 16 + ng) * 32 + lane]);
            float2 bl = __ldg(&g_Bl[WSEL][(ks * 16 + ng) * 32 + lane]);
            uint32_t bh0 = __float_as_uint(bh.x), bh1 = __float_as_uint(bh.y);
            uint32_t bl0 = __float_as_uint(bl.x), bl1 = __float_as_uint(bl.y);
#pragma unroll
            for (int mt = 0; mt < 2; mt++) {
                mma_tf32(acc[mt][nt], ah[mt], bh0, bh1);  // Ah*Bh
                mma_tf32(acc[mt][nt], al[mt], bh0, bh1);  // Al*Bh
                mma_tf32(acc[mt][nt], ah[mt], bl0, bl1);  // Ah*Bl
            }
        }
    }

    // epilogue
    float* Cout = DST ? C : g_bufA;
#pragma unroll
    for (int mt = 0; mt < 2; mt++) {
#pragma unroll
        for (int nt = 0; nt < 4; nt++) {
            int col = warpNg * 32 + nt * 8 + tid4 * 2;
            float bx = 0.f, by = 0.f;
            if (ADD_BIAS) {
                float2 bv = ((const float2*)bias)[col >> 1];
                bx = bv.x; by = bv.y;
            }
            int r0 = row0 + warpM + mt * 16 + gid;
            if (r0 < M) {
                float2 o = make_float2(acc[mt][nt][0] + bx, acc[mt][nt][1] + by);
                *(float2*)&Cout[(size_t)r0 * DIM + col] = o;
            }
            if (r0 + 8 < M) {
                float2 o = make_float2(acc[mt][nt][2] + bx, acc[mt][nt][3] + by);
                *(float2*)&Cout[(size_t)(r0 + 8) * DIM + col] = o;
            }
        }
    }
}

// ---------------- aggregation: out[i] = sum_j norm*h[src] + self + bias -------
// 4-deep unrolled CSR walk; packed (src, weight) int2 edge records
template <int DST_BUF, bool RELU>
__global__ void aggregate_kernel(const float* __restrict__ bias,
                                 float* __restrict__ out) {
    int node = blockIdx.x * 8 + threadIdx.y;
    if (node >= N_NODES) return;
    int lane = threadIdx.x;

    const float4* H4 = (const float4*)g_bufA;
    float di = g_dinv[node];
    float w0 = di * di;
    float4 h = H4[(size_t)node * 32 + lane];
    float4 acc = make_float4(h.x * w0, h.y * w0, h.z * w0, h.w * w0);

    int j = g_rowptr[node];
    int end = g_rowend[node];
    for (; j + 3 < end; j += 4) {
        int2 e0 = g_csre[j];
        int2 e1 = g_csre[j + 1];
        int2 e2 = g_csre[j + 2];
        int2 e3 = g_csre[j + 3];
        float wa = __int_as_float(e0.y);
        float wb = __int_as_float(e1.y);
        float wc = __int_as_float(e2.y);
        float wd = __int_as_float(e3.y);
        float4 v0 = H4[(size_t)e0.x * 32 + lane];
        float4 v1 = H4[(size_t)e1.x * 32 + lane];
        float4 v2 = H4[(size_t)e2.x * 32 + lane];
        float4 v3 = H4[(size_t)e3.x * 32 + lane];
        acc.x += v0.x * wa; acc.y += v0.y * wa;
        acc.z += v0.z * wa; acc.w += v0.w * wa;
        acc.x += v1.x * wb; acc.y += v1.y * wb;
        acc.z += v1.z * wb; acc.w += v1.w * wb;
        acc.x += v2.x * wc; acc.y += v2.y * wc;
        acc.z += v2.z * wc; acc.w += v2.w * wc;
        acc.x += v3.x * wd; acc.y += v3.y * wd;
        acc.z += v3.z * wd; acc.w += v3.w * wd;
    }
    for (; j < end; j++) {
        int2 e = g_csre[j];
        float w = __int_as_float(e.y);
        float4 v = H4[(size_t)e.x * 32 + lane];
        acc.x += v.x * w; acc.y += v.y * w;
        acc.z += v.z * w; acc.w += v.w * w;
    }

    float4 bv = ((const float4*)bias)[lane];
    acc.x += bv.x; acc.y += bv.y; acc.z += bv.z; acc.w += bv.w;
    if (RELU) {
        acc.x = fmaxf(acc.x, 0.f);
        acc.y = fmaxf(acc.y, 0.f);
        acc.z = fmaxf(acc.z, 0.f);
        acc.w = fmaxf(acc.w, 0.f);
    }
    float4* O = DST_BUF ? (float4*)g_bufB : (float4*)out;
    O[(size_t)node * 32 + lane] = acc;
}

// ---------------- launch (serial chain) ---------------------------------------
extern "C" void kernel_launch(void* const* d_in, const int* in_sizes, int n_in,
                              void* d_out, int out_size) {
    const float* x    = (const float*)d_in[0];
    const int*   ei   = (const int*)d_in[1];
    const float* qemb = (const float*)d_in[2];
    const float* W1   = (const float*)d_in[3];
    const float* b1   = (const float*)d_in[4];
    const float* W2   = (const float*)d_in[5];
    const float* b2   = (const float*)d_in[6];
    const float* Wq   = (const float*)d_in[7];
    const float* bq   = (const float*)d_in[8];

    float* out = (float*)d_out;
    float* out_ques = out;                          // [20000,128]
    float* out_h2   = out + (size_t)20000 * DIM;    // [50000,128]

    // weight packing + graph preprocessing (single-kernel scan)
    pack_w_kernel<<<(3 * 8192 + 255) / 256, 256>>>(W1, W2, Wq);
    count_kernel<<<(N_EDGES + 255) / 256, 256>>>(ei);
    scan_kernel<<<SCAN_NB, 256>>>();
    scatter_kernel<<<(N_EDGES / 2 + 255) / 256, 256>>>(ei);

    // layer 1: g_bufA = x @ W1 ; g_bufB = relu(agg(g_bufA) + b1)
    gemm_mma_kernel<0, 0, 0, false><<<(N_NODES + 63) / 64, 256>>>(x, nullptr, nullptr, N_NODES);
    aggregate_kernel<1, true><<<(N_NODES + 7) / 8, dim3(32, 8)>>>(b1, nullptr);
    // layer 2: g_bufA = g_bufB @ W2 ; out_h2 = agg(g_bufA) + b2
    gemm_mma_kernel<1, 1, 0, false><<<(N_NODES + 63) / 64, 256>>>(nullptr, nullptr, nullptr, N_NODES);
    aggregate_kernel<0, false><<<(N_NODES + 7) / 8, dim3(32, 8)>>>(b2, out_h2);
    // question path: ques = q_emb @ Wq + bq
    gemm_mma_kernel<2, 0, 1, true><<<(20000 + 63) / 64, 256>>>(qemb, bq, out_ques, 20000);
}